// round 16
// baseline (speedup 1.0000x reference)
#include <cuda_runtime.h>
#include <cstdint>
#include <stdint.h>
#include <math.h>

// ---------------------------------------------------------------------------
// Problem constants: B=2, S=2048, DIM=2048, H=16, HDIM=128
// ---------------------------------------------------------------------------
#define DIMV 2048
#define GM   4096      // B*S rows
#define SEQ  2048
#define NHEAD 16
#define HDIM 128

// Scratch (device globals: allocation-free per harness rules)
__device__ float g_qr [GM * DIMV];          // rope'd + scaled(+log2e) tf32 q
__device__ float g_kr [GM * DIMV];          // rope'd + tf32 k
__device__ float g_v  [GM * DIMV];          // tf32 v
__device__ float g_att[GM * DIMV];
__device__ float g_xr [GM * DIMV];          // tf32-rounded x
__device__ float g_wqr[DIMV * DIMV];        // tf32-rounded weights
__device__ float g_wkr[DIMV * DIMV];
__device__ float g_wvr[DIMV * DIMV];
__device__ float g_wor[DIMV * DIMV];
__device__ float g_tcos[SEQ * 64];
__device__ float g_tsin[SEQ * 64];
__device__ float g_invf[64];

// ---------------------------------------------------------------------------
// Helpers
// ---------------------------------------------------------------------------
__device__ __forceinline__ float tf32r(float x) {
    unsigned u;
    asm("cvt.rna.tf32.f32 %0, %1;" : "=r"(u) : "f"(x));
    return __uint_as_float(u);
}

__device__ __forceinline__ unsigned smem_u32(const void* p) {
    return (unsigned)__cvta_generic_to_shared(p);
}

#define CP_ASYNC16(dst_u32, src) \
    asm volatile("cp.async.cg.shared.global [%0], [%1], 16;\n" :: "r"(dst_u32), "l"(src))
#define CP_COMMIT() asm volatile("cp.async.commit_group;\n" ::)
#define CP_WAIT1()  asm volatile("cp.async.wait_group 1;\n" ::)
#define CP_WAIT0()  asm volatile("cp.async.wait_group 0;\n" ::)

// ldmatrix x4: four 8x8 b16 matrices == four 8x4 f32 blocks.
#define LDSM_X4(r0, r1, r2, r3, addr) \
    asm volatile("ldmatrix.sync.aligned.m8n8.x4.shared.b16 {%0,%1,%2,%3}, [%4];" \
                 : "=r"(r0), "=r"(r1), "=r"(r2), "=r"(r3) : "r"(addr))

// mma.sync m16n8k8 tf32 fp32-accum (row.col), operands as raw b32.
// A: a0=(g,c) a1=(g+8,c) a2=(g,c+4) a3=(g+8,c+4)   [g=lane>>2, c=lane&3]
// B: b0=(k=c,n=g) b1=(k=c+4,n=g)
// C: c0=(g,2c) c1=(g,2c+1) c2=(g+8,2c) c3=(g+8,2c+1)
__device__ __forceinline__ void mma8u(float* d, const uint32_t* a,
                                      uint32_t b0, uint32_t b1) {
    asm volatile(
        "mma.sync.aligned.m16n8k8.row.col.f32.tf32.tf32.f32 "
        "{%0,%1,%2,%3}, {%4,%5,%6,%7}, {%8,%9}, {%0,%1,%2,%3};\n"
        : "+f"(d[0]), "+f"(d[1]), "+f"(d[2]), "+f"(d[3])
        : "r"(a[0]), "r"(a[1]), "r"(a[2]), "r"(a[3]), "r"(b0), "r"(b1));
}

// ---------------------------------------------------------------------------
// Fused tf32 pre-round of x + all 4 weights (one launch, MLP=4)
// ---------------------------------------------------------------------------
#define NX4 (GM * DIMV / 4)       // 2097152 float4
#define NW4 (DIMV * DIMV / 4)     // 1048576 float4
#define NALL4 (NX4 + 4 * NW4)     // 6291456

__global__ void round_all(const float* __restrict__ x,
                          const float* __restrict__ wq,
                          const float* __restrict__ wk,
                          const float* __restrict__ wv,
                          const float* __restrict__ wo) {
    long long base = (long long)blockIdx.x * (blockDim.x * 4) + threadIdx.x;
#pragma unroll
    for (int u = 0; u < 4; u++) {
        long long i = base + (long long)u * blockDim.x;
        if (i >= NALL4) return;
        const float4* src;
        float4* dst;
        long long off;
        if (i < NX4) {
            src = (const float4*)x;  dst = (float4*)g_xr;  off = i;
        } else {
            long long j = i - NX4;
            int r = (int)(j / NW4);
            off = j % NW4;
            if (r == 0)      { src = (const float4*)wq; dst = (float4*)g_wqr; }
            else if (r == 1) { src = (const float4*)wk; dst = (float4*)g_wkr; }
            else if (r == 2) { src = (const float4*)wv; dst = (float4*)g_wvr; }
            else             { src = (const float4*)wo; dst = (float4*)g_wor; }
        }
        float4 v = src[off];
        v.x = tf32r(v.x); v.y = tf32r(v.y); v.z = tf32r(v.z); v.w = tf32r(v.w);
        dst[off] = v;
    }
}

// ---------------------------------------------------------------------------
// RoPE tables. 64 distinct inv_freq via tiny FP64 kernel; float table build.
// ---------------------------------------------------------------------------
__global__ void invf_kernel() {
    int j = threadIdx.x;
    if (j < 64)
        g_invf[j] = (float)exp(-(double)j * 0.14391156831212787);  // ln(1e4)/64
}

__global__ void rope_tables() {
    int idx = blockIdx.x * blockDim.x + threadIdx.x;
    if (idx >= SEQ * 64) return;
    int s = idx >> 6, j = idx & 63;
    float a = (float)s * g_invf[j];
    float sn, cs;
    sincosf(a, &sn, &cs);
    g_tcos[idx] = cs;
    g_tsin[idx] = sn;
}

// ---------------------------------------------------------------------------
// GEMM (NT): R10-shape body (128x128x32 tile, 256 threads, 64x32 warp tiles,
// 3-stage cp.async, one barrier per k-tile, LDSM frag loads, 2 CTAs/SM),
// now with a GRID-STRIDE TILE LOOP for wave packing: QKV launches 1480 CTAs
// (= 5 x 296 concurrent slots) over 1536 tiles, so bids 0..55 run two tiles
// and the makespan drops from 6 waves to ~5.2.
// Tile id tt -> matrix z = tt>>9, y = (tt>>4)&31, x = tt&15.
// Epilogue modes: 0 plain fp32; 1 RoPE + (log2e/sqrt(128)) + tf32 (Q);
// 2 RoPE + tf32 (K); 3 tf32 (V).
// ---------------------------------------------------------------------------
#define GSTR 36
#define STAGE_F (2 * 128 * GSTR)          // floats per stage (A + B)
#define GEMM_SMEM (3 * STAGE_F * 4)       // 110592 B -> 2 CTAs/SM

__global__ __launch_bounds__(256, 2) void gemm_nt(
    const float* __restrict__ A,
    const float* __restrict__ B0, const float* __restrict__ B1,
    const float* __restrict__ B2,
    float* __restrict__ C0, float* __restrict__ C1, float* __restrict__ C2,
    int m0, int m1, int m2, int total_tiles) {
    extern __shared__ float sm[];

    const int tid  = threadIdx.x;
    const int lane = tid & 31;
    const int wid  = tid >> 5;
    const int g    = lane >> 2;
    const int c    = lane & 3;
    const int wm   = wid & 1;
    const int wn   = wid >> 1;

    const int lr = tid >> 3;         // 0..31
    const int lc = (tid & 7) << 2;   // 0..28 step 4

    const unsigned smB = smem_u32(sm);
    const unsigned SSZ = STAGE_F * 4;            // stage bytes
    const unsigned stA = smB + (lr * GSTR + lc) * 4;
    const unsigned stB = stA + 128 * GSTR * 4;

    // LDSM per-lane offsets (bytes, within a stage)
    const int lm = lane >> 3, lrr = lane & 7;
    unsigned offA[4], offB[2];
#pragma unroll
    for (int mf = 0; mf < 4; mf++)
        offA[mf] = (unsigned)(((wm * 64 + mf * 16 + (lm & 1) * 8 + lrr) * GSTR
                               + (lm >> 1) * 4) * 4);
#pragma unroll
    for (int p = 0; p < 2; p++)
        offB[p] = (unsigned)((128 * GSTR
                              + (wn * 32 + p * 16 + (lm >> 1) * 8 + lrr) * GSTR
                              + (lm & 1) * 4) * 4);

    for (int tt = blockIdx.x; tt < total_tiles; tt += gridDim.x) {
        const int z = tt >> 9;                 // 512 tiles per matrix
        const float* __restrict__ B = (z == 0) ? B0 : (z == 1) ? B1 : B2;
        float* __restrict__ C       = (z == 0) ? C0 : (z == 1) ? C1 : C2;
        const int mode              = (z == 0) ? m0 : (z == 1) ? m1 : m2;
        const int mbase = ((tt >> 4) & 31) * 128;
        const int nbase = (tt & 15) * 128;

        const float* Ap = A + (size_t)(mbase + lr) * DIMV + lc;
        const float* Bp = B + (size_t)(nbase + lr) * DIMV + lc;

        __syncthreads();   // prior tile's smem reads fully done before restage

        float acc[4][4][4];
#pragma unroll
        for (int i = 0; i < 4; i++)
#pragma unroll
            for (int j = 0; j < 4; j++)
#pragma unroll
                for (int e = 0; e < 4; e++) acc[i][j][e] = 0.f;

        auto issue = [&](int t) {
            const unsigned so = (unsigned)(t % 3) * SSZ;
            const float* An = Ap + t * 32;
            const float* Bn = Bp + t * 32;
#pragma unroll
            for (int r = 0; r < 4; r++) {
                CP_ASYNC16(stA + so + r * 32 * GSTR * 4, An + (size_t)r * 32 * DIMV);
                CP_ASYNC16(stB + so + r * 32 * GSTR * 4, Bn + (size_t)r * 32 * DIMV);
            }
            CP_COMMIT();
        };
        issue(0);
        issue(1);

        const int NT = DIMV / 32;
        for (int t = 0; t < NT; t++) {
            if (t + 1 < NT) { CP_WAIT1(); } else { CP_WAIT0(); }
            __syncthreads();               // stage t visible; WAR (t+2)%3
            if (t + 2 < NT) issue(t + 2);

            const unsigned base = smB + (unsigned)(t % 3) * SSZ;
#pragma unroll
            for (int kk = 0; kk < 4; kk++) {
                const unsigned kb = kk * 32;   // 8 floats
                uint32_t a[4][4];
#pragma unroll
                for (int mf = 0; mf < 4; mf++)
                    LDSM_X4(a[mf][0], a[mf][1], a[mf][2], a[mf][3],
                            base + offA[mf] + kb);
                uint32_t bfr[2][4];
#pragma unroll
                for (int p = 0; p < 2; p++)
                    LDSM_X4(bfr[p][0], bfr[p][1], bfr[p][2], bfr[p][3],
                            base + offB[p] + kb);
#pragma unroll
                for (int nf = 0; nf < 4; nf++) {
                    const uint32_t b0 = bfr[nf >> 1][(nf & 1) * 2];
                    const uint32_t b1 = bfr[nf >> 1][(nf & 1) * 2 + 1];
#pragma unroll
                    for (int mf = 0; mf < 4; mf++)
                        mma8u(acc[mf][nf], a[mf], b0, b1);
                }
            }
        }

        if (mode == 1 || mode == 2) {
            __syncthreads();   // compute done before reusing pipeline smem
            float* Cs = sm;    // 128 x 132 floats = 67584 B
#pragma unroll
            for (int mf = 0; mf < 4; mf++) {
                const int row = wm * 64 + mf * 16 + g;
#pragma unroll
                for (int nf = 0; nf < 4; nf++) {
                    const int col = wn * 32 + nf * 8 + 2 * c;
                    *(float2*)&Cs[row * 132 + col] =
                        make_float2(acc[mf][nf][0], acc[mf][nf][1]);
                    *(float2*)&Cs[(row + 8) * 132 + col] =
                        make_float2(acc[mf][nf][2], acc[mf][nf][3]);
                }
            }
            __syncthreads();
            // mode 1: log2(e)/sqrt(128) -> exp2-domain softmax downstream
            const float SC = (mode == 1) ? 0.12751747707857376f : 1.0f;
            for (int p = tid; p < 128 * 32; p += 256) {
                const int r  = p >> 5;
                const int f4 = (p & 31) << 2;
                const int m  = mbase + r;
                const int s  = m & (SEQ - 1);
                const float* crow = &Cs[r * 132];
                float v[4];
                if (f4 < 64) {
#pragma unroll
                    for (int e = 0; e < 4; e++) {
                        const int j = f4 + e;
                        const float cs = g_tcos[(s << 6) + j];
                        const float sn = g_tsin[(s << 6) + j];
                        v[e] = tf32r((crow[j] * cs - crow[2 * j + 1] * sn) * SC);
                    }
                } else {
#pragma unroll
                    for (int e = 0; e < 4; e++) {
                        const int j = f4 - 64 + e;
                        const float cs = g_tcos[(s << 6) + j];
                        const float sn = g_tsin[(s << 6) + j];
                        v[e] = tf32r((crow[j + 64] * cs + crow[2 * j] * sn) * SC);
                    }
                }
                *(float4*)&C[(size_t)m * DIMV + nbase + f4] =
                    make_float4(v[0], v[1], v[2], v[3]);
            }
        } else {
#pragma unroll
            for (int mf = 0; mf < 4; mf++) {
                const int row = mbase + wm * 64 + mf * 16 + g;
#pragma unroll
                for (int nf = 0; nf < 4; nf++) {
                    const int col = nbase + wn * 32 + nf * 8 + 2 * c;
                    float o0 = acc[mf][nf][0], o1 = acc[mf][nf][1];
                    float o2 = acc[mf][nf][2], o3 = acc[mf][nf][3];
                    if (mode == 3) {
                        o0 = tf32r(o0); o1 = tf32r(o1);
                        o2 = tf32r(o2); o3 = tf32r(o3);
                    }
                    *(float2*)&C[(size_t)row * DIMV + col] = make_float2(o0, o1);
                    *(float2*)&C[(size_t)(row + 8) * DIMV + col] =
                        make_float2(o2, o3);
                }
            }
        }
    }
}

// ---------------------------------------------------------------------------
// Causal flash attention (unchanged from R15). One CTA processes the q-tile
// pair (31-i, i): every CTA does exactly 33 kv-iters. exp2-domain softmax.
// Bkv=64; split cp.async commit groups; P aliases K; LDSM frag loads.
// 102400 B smem -> 2 CTAs/SM.
// ---------------------------------------------------------------------------
#define QSTR 132
#define KSTR 132
#define VSTR 136
#define PSTR 68
#define KOFS (64 * QSTR)
#define VOFS (KOFS + 64 * KSTR)
#define FLASH_SMEM ((VOFS + 64 * VSTR) * 4)   // 102400

__global__ __launch_bounds__(128) void flash_kernel() {
    extern __shared__ float sm[];
    float* Qs = sm;
    float* Ks = sm + KOFS;     // re-used as P after the S phase
    float* Vs = sm + VOFS;

    const int tid  = threadIdx.x;
    const int lane = tid & 31;
    const int w    = tid >> 5;
    const int g    = lane >> 2;
    const int c    = lane & 3;

    const int h  = blockIdx.y;
    const int b  = blockIdx.z;
    const size_t brow = (size_t)b * SEQ;
    const int hcol = h * HDIM;
    const int NQT = SEQ / 64;   // 32

    const unsigned smB = smem_u32(sm);
    const int lm = lane >> 3, lrr = lane & 7;
    const unsigned offQ = (unsigned)(((w * 16 + (lm & 1) * 8 + lrr) * QSTR
                                      + (lm >> 1) * 4) * 4);
    unsigned offK[4];
#pragma unroll
    for (int p = 0; p < 4; p++)
        offK[p] = (unsigned)((KOFS + (p * 16 + (lm >> 1) * 8 + lrr) * KSTR
                              + (lm & 1) * 4) * 4);
    const unsigned offP = (unsigned)((KOFS + w * 16 * PSTR
                                      + ((lm & 1) * 8 + lrr) * PSTR
                                      + (lm >> 1) * 4) * 4);

    float* Pw = Ks + w * 16 * PSTR;   // alias into K region

    for (int half = 0; half < 2; half++) {
        const int qt = (half == 0) ? (NQT - 1 - (int)blockIdx.x)
                                   : (int)blockIdx.x;
        const int q0 = qt * 64;

        __syncthreads();   // prior half's P/V smem reads fully done

        for (int idx = tid; idx < 64 * 32; idx += 128) {
            int r = idx >> 5, d4 = (idx & 31) << 2;
            CP_ASYNC16(smem_u32(&Qs[r * QSTR + d4]),
                       &g_qr[(brow + q0 + r) * DIMV + hcol + d4]);
        }
        CP_COMMIT();

        float O[16][4];
#pragma unroll
        for (int nf = 0; nf < 16; nf++)
#pragma unroll
            for (int e = 0; e < 4; e++) O[nf][e] = 0.f;
        float m0 = -1e30f, m1 = -1e30f, l0 = 0.f, l1 = 0.f;

        for (int kt = 0; kt <= qt; kt++) {
            __syncthreads();
            for (int idx = tid; idx < 64 * 32; idx += 128) {
                int r = idx >> 5, d4 = (idx & 31) << 2;
                CP_ASYNC16(smem_u32(&Ks[r * KSTR + d4]),
                           &g_kr[(brow + (size_t)kt * 64 + r) * DIMV + hcol + d4]);
            }
            CP_COMMIT();
            for (int idx = tid; idx < 64 * 32; idx += 128) {
                int r = idx >> 5, d4 = (idx & 31) << 2;
                CP_ASYNC16(smem_u32(&Vs[r * VSTR + d4]),
                           &g_v[(brow + (size_t)kt * 64 + r) * DIMV + hcol + d4]);
            }
            CP_COMMIT();
            CP_WAIT1();
            __syncthreads();

            float sacc[8][4];
#pragma unroll
            for (int nf = 0; nf < 8; nf++)
#pragma unroll
                for (int e = 0; e < 4; e++) sacc[nf][e] = 0.f;

#pragma unroll
            for (int k0 = 0; k0 < 128; k0 += 8) {
                uint32_t a[4];
                LDSM_X4(a[0], a[1], a[2], a[3], smB + offQ + k0 * 4);
                uint32_t kb[4][4];
#pragma unroll
                for (int p = 0; p < 4; p++)
                    LDSM_X4(kb[p][0], kb[p][1], kb[p][2], kb[p][3],
                            smB + offK[p] + k0 * 4);
#pragma unroll
                for (int nf = 0; nf < 8; nf++)
                    mma8u(sacc[nf], a, kb[nf >> 1][(nf & 1) * 2],
                          kb[nf >> 1][(nf & 1) * 2 + 1]);
            }

            if (kt == qt) {
                const int r0 = w * 16 + g;
#pragma unroll
                for (int nf = 0; nf < 8; nf++) {
                    const int col0 = nf * 8 + 2 * c;
                    if (col0     > r0)     sacc[nf][0] = -1e30f;
                    if (col0 + 1 > r0)     sacc[nf][1] = -1e30f;
                    if (col0     > r0 + 8) sacc[nf][2] = -1e30f;
                    if (col0 + 1 > r0 + 8) sacc[nf][3] = -1e30f;
                }
            }

            float rm0 = -1e30f, rm1 = -1e30f;
#pragma unroll
            for (int nf = 0; nf < 8; nf++) {
                rm0 = fmaxf(rm0, fmaxf(sacc[nf][0], sacc[nf][1]));
                rm1 = fmaxf(rm1, fmaxf(sacc[nf][2], sacc[nf][3]));
            }
            rm0 = fmaxf(rm0, __shfl_xor_sync(0xffffffffu, rm0, 1));
            rm0 = fmaxf(rm0, __shfl_xor_sync(0xffffffffu, rm0, 2));
            rm1 = fmaxf(rm1, __shfl_xor_sync(0xffffffffu, rm1, 1));
            rm1 = fmaxf(rm1, __shfl_xor_sync(0xffffffffu, rm1, 2));

            const float mn0 = fmaxf(m0, rm0), mn1 = fmaxf(m1, rm1);
            const float al0 = exp2f(m0 - mn0), al1 = exp2f(m1 - mn1);

            float ps0 = 0.f, ps1 = 0.f;
#pragma unroll
            for (int nf = 0; nf < 8; nf++) {   // pure MUFU.EX2
                sacc[nf][0] = exp2f(sacc[nf][0] - mn0);
                sacc[nf][1] = exp2f(sacc[nf][1] - mn0);
                sacc[nf][2] = exp2f(sacc[nf][2] - mn1);
                sacc[nf][3] = exp2f(sacc[nf][3] - mn1);
                ps0 += sacc[nf][0] + sacc[nf][1];
                ps1 += sacc[nf][2] + sacc[nf][3];
            }
            ps0 += __shfl_xor_sync(0xffffffffu, ps0, 1);
            ps0 += __shfl_xor_sync(0xffffffffu, ps0, 2);
            ps1 += __shfl_xor_sync(0xffffffffu, ps1, 1);
            ps1 += __shfl_xor_sync(0xffffffffu, ps1, 2);
            l0 = l0 * al0 + ps0;
            l1 = l1 * al1 + ps1;
            m0 = mn0; m1 = mn1;

#pragma unroll
            for (int nf = 0; nf < 16; nf++) {
                O[nf][0] *= al0; O[nf][1] *= al0;
                O[nf][2] *= al1; O[nf][3] *= al1;
            }

            CP_WAIT0();        // V landed
            __syncthreads();   // all warps done READING K before P overwrites

#pragma unroll
            for (int nf = 0; nf < 8; nf++) {
                const int col = nf * 8 + 2 * c;
                *(float2*)&Pw[g * PSTR + col] =
                    make_float2(tf32r(sacc[nf][0]), tf32r(sacc[nf][1]));
                *(float2*)&Pw[(g + 8) * PSTR + col] =
                    make_float2(tf32r(sacc[nf][2]), tf32r(sacc[nf][3]));
            }
            __syncwarp();

#pragma unroll
            for (int k0 = 0; k0 < 64; k0 += 8) {
                uint32_t a[4];
                LDSM_X4(a[0], a[1], a[2], a[3], smB + offP + k0 * 4);
#pragma unroll
                for (int nf = 0; nf < 16; nf++) {
                    const uint32_t b0 =
                        __float_as_uint(Vs[(k0 + c) * VSTR + nf * 8 + g]);
                    const uint32_t b1 =
                        __float_as_uint(Vs[(k0 + c + 4) * VSTR + nf * 8 + g]);
                    mma8u(O[nf], a, b0, b1);
                }
            }
        }

        const float r0 = 1.f / l0, r1 = 1.f / l1;
        const int qrow = q0 + w * 16 + g;
#pragma unroll
        for (int nf = 0; nf < 16; nf++) {
            const int col = hcol + nf * 8 + 2 * c;
            *(float2*)&g_att[(brow + qrow) * DIMV + col] =
                make_float2(tf32r(O[nf][0] * r0), tf32r(O[nf][1] * r0));
            *(float2*)&g_att[(brow + qrow + 8) * DIMV + col] =
                make_float2(tf32r(O[nf][2] * r1), tf32r(O[nf][3] * r1));
        }
    }
}

// ---------------------------------------------------------------------------
// Launch. 7 launches; the idempotent invf re-launch before flash makes
// flash the 6th launch -> ncu (-s 5 -c 1) captures FLASH this round.
// ---------------------------------------------------------------------------
extern "C" void kernel_launch(void* const* d_in, const int* in_sizes, int n_in,
                              void* d_out, int out_size) {
    (void)in_sizes; (void)n_in; (void)out_size;
    const float* x  = (const float*)d_in[0];
    const float* Wq = (const float*)d_in[1];
    const float* Wk = (const float*)d_in[2];
    const float* Wv = (const float*)d_in[3];
    const float* Wo = (const float*)d_in[4];
    float* out = (float*)d_out;

    float *pqr, *pkr, *pv, *patt, *pxr, *pwq, *pwk, *pwv, *pwo;
    cudaGetSymbolAddress((void**)&pqr,  g_qr);
    cudaGetSymbolAddress((void**)&pkr,  g_kr);
    cudaGetSymbolAddress((void**)&pv,   g_v);
    cudaGetSymbolAddress((void**)&patt, g_att);
    cudaGetSymbolAddress((void**)&pxr,  g_xr);
    cudaGetSymbolAddress((void**)&pwq,  g_wqr);
    cudaGetSymbolAddress((void**)&pwk,  g_wkr);
    cudaGetSymbolAddress((void**)&pwv,  g_wvr);
    cudaGetSymbolAddress((void**)&pwo,  g_wor);

    cudaFuncSetAttribute(gemm_nt,
                         cudaFuncAttributeMaxDynamicSharedMemorySize, GEMM_SMEM);
    cudaFuncSetAttribute(flash_kernel,
                         cudaFuncAttributeMaxDynamicSharedMemorySize, FLASH_SMEM);

    round_all<<<(NALL4 + 1023) / 1024, 256>>>(x, Wq, Wk, Wv, Wo);   // 1
    invf_kernel<<<1, 64>>>();                                       // 2
    rope_tables<<<(SEQ * 64 + 255) / 256, 256>>>();                 // 3

    // QKV fused: 1536 tiles over 1480 CTAs (5 exact waves at 2 CTAs/SM)
    gemm_nt<<<1480, 256, GEMM_SMEM>>>(pxr, pwq, pwk, pwv,
                                      pqr, pkr, pv, 1, 2, 3, 1536); // 4
    invf_kernel<<<1, 64>>>();   // idempotent; aligns ncu capture    // 5
    flash_kernel<<<dim3(SEQ / 128, NHEAD, 2), 128, FLASH_SMEM>>>(); // 6 (ncu)
    // Output projection: 512 tiles, one per CTA
    gemm_nt<<<512, 256, GEMM_SMEM>>>(patt, pwo, pwo, pwo,
                                     out, out, out, 0, 0, 0, 512);  // 7
}

// round 17
// speedup vs baseline: 1.4164x; 1.4164x over previous
#include <cuda_runtime.h>
#include <cuda_fp16.h>
#include <cstdint>
#include <stdint.h>
#include <math.h>

// ---------------------------------------------------------------------------
// Problem constants: B=2, S=2048, DIM=2048, H=16, HDIM=128
// ---------------------------------------------------------------------------
#define DIMV 2048
#define GM   4096      // B*S rows
#define SEQ  2048
#define NHEAD 16
#define HDIM 128

// Scratch (device globals: allocation-free per harness rules)
__device__ float  g_qr [GM * DIMV];         // rope'd + scaled(+log2e) tf32 q
__device__ float  g_kr [GM * DIMV];         // rope'd + tf32 k
__device__ float  g_v  [GM * DIMV];         // tf32 v
__device__ __half g_att[GM * DIMV];         // flash out (half: feeds Wo GEMM)
__device__ __half g_xh [GM * DIMV];         // fp16 x
__device__ __half g_wqh[DIMV * DIMV];       // fp16 weights
__device__ __half g_wkh[DIMV * DIMV];
__device__ __half g_wvh[DIMV * DIMV];
__device__ __half g_woh[DIMV * DIMV];
__device__ float  g_tcos[SEQ * 64];
__device__ float  g_tsin[SEQ * 64];
__device__ float  g_invf[64];

// ---------------------------------------------------------------------------
// Helpers
// ---------------------------------------------------------------------------
__device__ __forceinline__ float tf32r(float x) {
    unsigned u;
    asm("cvt.rna.tf32.f32 %0, %1;" : "=r"(u) : "f"(x));
    return __uint_as_float(u);
}

__device__ __forceinline__ unsigned smem_u32(const void* p) {
    return (unsigned)__cvta_generic_to_shared(p);
}

#define CP_ASYNC16(dst_u32, src) \
    asm volatile("cp.async.cg.shared.global [%0], [%1], 16;\n" :: "r"(dst_u32), "l"(src))
#define CP_COMMIT() asm volatile("cp.async.commit_group;\n" ::)
#define CP_WAIT1()  asm volatile("cp.async.wait_group 1;\n" ::)
#define CP_WAIT0()  asm volatile("cp.async.wait_group 0;\n" ::)

// ldmatrix x4 (b16): four 8x8 b16 matrices; thread t of matrix m receives
// the half-pair at (row t/4, cols 2(t%4), 2(t%4)+1).
#define LDSM_X4(r0, r1, r2, r3, addr) \
    asm volatile("ldmatrix.sync.aligned.m8n8.x4.shared.b16 {%0,%1,%2,%3}, [%4];" \
                 : "=r"(r0), "=r"(r1), "=r"(r2), "=r"(r3) : "r"(addr))

// fp16 mma m16n8k16, fp32 accum (row.col).  [g=lane>>2, c=lane&3]
//   A(16x16): a0=(g,2c:2c+1) a1=(g+8,2c:2c+1) a2=(g,2c+8:+9) a3=(g+8,2c+8:+9)
//   B(16x8):  b0=(k=2c:2c+1, n=g)  b1=(k=2c+8:+9, n=g)
//   C: c0=(g,2c) c1=(g,2c+1) c2=(g+8,2c) c3=(g+8,2c+1)
__device__ __forceinline__ void mma16h(float* d, const uint32_t* a,
                                       uint32_t b0, uint32_t b1) {
    asm volatile(
        "mma.sync.aligned.m16n8k16.row.col.f32.f16.f16.f32 "
        "{%0,%1,%2,%3}, {%4,%5,%6,%7}, {%8,%9}, {%0,%1,%2,%3};\n"
        : "+f"(d[0]), "+f"(d[1]), "+f"(d[2]), "+f"(d[3])
        : "r"(a[0]), "r"(a[1]), "r"(a[2]), "r"(a[3]), "r"(b0), "r"(b1));
}

// tf32 mma m16n8k8 (flash only; unchanged proven path)
__device__ __forceinline__ void mma8u(float* d, const uint32_t* a,
                                      uint32_t b0, uint32_t b1) {
    asm volatile(
        "mma.sync.aligned.m16n8k8.row.col.f32.tf32.tf32.f32 "
        "{%0,%1,%2,%3}, {%4,%5,%6,%7}, {%8,%9}, {%0,%1,%2,%3};\n"
        : "+f"(d[0]), "+f"(d[1]), "+f"(d[2]), "+f"(d[3])
        : "r"(a[0]), "r"(a[1]), "r"(a[2]), "r"(a[3]), "r"(b0), "r"(b1));
}

// ---------------------------------------------------------------------------
// Fused fp16 pre-round of x + all 4 weights (one launch, MLP=4)
// ---------------------------------------------------------------------------
#define NX4 (GM * DIMV / 4)       // float4 count for x
#define NW4 (DIMV * DIMV / 4)
#define NALL4 (NX4 + 4 * NW4)

__global__ void round_all(const float* __restrict__ x,
                          const float* __restrict__ wq,
                          const float* __restrict__ wk,
                          const float* __restrict__ wv,
                          const float* __restrict__ wo) {
    long long base = (long long)blockIdx.x * (blockDim.x * 4) + threadIdx.x;
#pragma unroll
    for (int u = 0; u < 4; u++) {
        long long i = base + (long long)u * blockDim.x;
        if (i >= NALL4) return;
        const float4* src;
        __half2* dst;
        long long off;
        if (i < NX4) {
            src = (const float4*)x;  dst = (__half2*)g_xh;  off = i;
        } else {
            long long j = i - NX4;
            int r = (int)(j / NW4);
            off = j % NW4;
            if (r == 0)      { src = (const float4*)wq; dst = (__half2*)g_wqh; }
            else if (r == 1) { src = (const float4*)wk; dst = (__half2*)g_wkh; }
            else if (r == 2) { src = (const float4*)wv; dst = (__half2*)g_wvh; }
            else             { src = (const float4*)wo; dst = (__half2*)g_woh; }
        }
        float4 v = src[off];
        dst[off * 2]     = __floats2half2_rn(v.x, v.y);
        dst[off * 2 + 1] = __floats2half2_rn(v.z, v.w);
    }
}

// ---------------------------------------------------------------------------
// RoPE tables. 64 distinct inv_freq via tiny FP64 kernel; float table build.
// ---------------------------------------------------------------------------
__global__ void invf_kernel() {
    int j = threadIdx.x;
    if (j < 64)
        g_invf[j] = (float)exp(-(double)j * 0.14391156831212787);  // ln(1e4)/64
}

__global__ void rope_tables() {
    int idx = blockIdx.x * blockDim.x + threadIdx.x;
    if (idx >= SEQ * 64) return;
    int s = idx >> 6, j = idx & 63;
    float a = (float)s * g_invf[j];
    float sn, cs;
    sincosf(a, &sn, &cs);
    g_tcos[idx] = cs;
    g_tsin[idx] = sn;
}

// ---------------------------------------------------------------------------
// fp16 GEMM (NT): C[4096,2048] = A[4096,2048] * W[2048,2048]^T (A,W half,
// acc f32). R10 structure: CTA 128x128, 256 threads, 64x32 warp tiles,
// 3-stage cp.async, one barrier per k-tile, LDSM frag loads. K-tile = 64
// HALVES (4 x k16 mma steps) -> NT = 32. Row stride 72 halves = 144 B
// == 4 mod 32 banks: identical conflict-free math to the f32 GSTR=36 case.
// Grid-stride tile loop; tile tt -> z=tt>>9, y=(tt>>4)&31, x=tt&15.
// Epilogue modes: 0 plain f32 (to d_out); 1 RoPE+(log2e/sqrt128)+tf32 (Q);
// 2 RoPE+tf32 (K); 3 tf32 (V). Outputs f32 for the tf32 flash.
// ---------------------------------------------------------------------------
#define HSTR 72                            // halves per row
#define TILE_H (128 * HSTR)                // halves per matrix per stage
#define STAGE_B (2 * TILE_H * 2)           // stage bytes = 36864
#define GEMM_SMEM (3 * STAGE_B)            // 110592 B -> 2 CTAs/SM

__global__ __launch_bounds__(256, 2) void gemm_nt(
    const __half* __restrict__ A,
    const __half* __restrict__ B0, const __half* __restrict__ B1,
    const __half* __restrict__ B2,
    float* __restrict__ C0, float* __restrict__ C1, float* __restrict__ C2,
    int m0, int m1, int m2, int total_tiles) {
    extern __shared__ float sm[];

    const int tid  = threadIdx.x;
    const int lane = tid & 31;
    const int wid  = tid >> 5;
    const int g    = lane >> 2;
    const int c    = lane & 3;
    const int wm   = wid & 1;
    const int wn   = wid >> 1;

    const int lr  = tid >> 3;        // 0..31 (row group)
    const int lc8 = tid & 7;         // 16B chunk (8 halves)

    const unsigned smB = smem_u32(sm);
    const unsigned stA = smB + (lr * HSTR + lc8 * 8) * 2;
    const unsigned stB = stA + TILE_H * 2;

    // LDSM per-lane offsets (bytes within a stage).
    // A x4 tile (16r x 16k): m0=(r0-7,k0-7) m1=(r8-15,k0-7) m2=(r0-7,k8-15)
    // m3=(r8-15,k8-15) -> regs a0..a3 in exactly the mma A-frag order.
    const int lm = lane >> 3, lrr = lane & 7;
    unsigned offA[4], offB[2];
#pragma unroll
    for (int mf = 0; mf < 4; mf++)
        offA[mf] = (unsigned)(((wm * 64 + mf * 16 + (lm & 1) * 8 + lrr) * HSTR
                               + (lm >> 1) * 8) * 2);
    // B x4 tile (16n x 16k): m0=(n0-7,k0-7) m1=(n8-15,k0-7) m2=(n0-7,k8-15)
    // m3=(n8-15,k8-15); nf even: b0=r0,b1=r2; nf odd: b0=r1,b1=r3.
#pragma unroll
    for (int p = 0; p < 2; p++)
        offB[p] = (unsigned)((TILE_H
                              + (wn * 32 + p * 16 + (lm & 1) * 8 + lrr) * HSTR
                              + (lm >> 1) * 8) * 2);

    for (int tt = blockIdx.x; tt < total_tiles; tt += gridDim.x) {
        const int z = tt >> 9;
        const __half* __restrict__ B = (z == 0) ? B0 : (z == 1) ? B1 : B2;
        float* __restrict__ C        = (z == 0) ? C0 : (z == 1) ? C1 : C2;
        const int mode               = (z == 0) ? m0 : (z == 1) ? m1 : m2;
        const int mbase = ((tt >> 4) & 31) * 128;
        const int nbase = (tt & 15) * 128;

        const __half* Ap = A + (size_t)(mbase + lr) * DIMV + lc8 * 8;
        const __half* Bp = B + (size_t)(nbase + lr) * DIMV + lc8 * 8;

        __syncthreads();   // prior tile's smem use done before restaging

        float acc[4][4][4];
#pragma unroll
        for (int i = 0; i < 4; i++)
#pragma unroll
            for (int j = 0; j < 4; j++)
#pragma unroll
                for (int e = 0; e < 4; e++) acc[i][j][e] = 0.f;

        auto issue = [&](int t) {
            const unsigned so = (unsigned)(t % 3) * STAGE_B;
            const __half* An = Ap + t * 64;
            const __half* Bn = Bp + t * 64;
#pragma unroll
            for (int r = 0; r < 4; r++) {
                CP_ASYNC16(stA + so + r * 32 * HSTR * 2, An + (size_t)r * 32 * DIMV);
                CP_ASYNC16(stB + so + r * 32 * HSTR * 2, Bn + (size_t)r * 32 * DIMV);
            }
            CP_COMMIT();
        };
        issue(0);
        issue(1);

        const int NT = DIMV / 64;          // 32
        for (int t = 0; t < NT; t++) {
            if (t + 1 < NT) { CP_WAIT1(); } else { CP_WAIT0(); }
            __syncthreads();               // stage t visible; WAR (t+2)%3
            if (t + 2 < NT) issue(t + 2);

            const unsigned base = smB + (unsigned)(t % 3) * STAGE_B;
#pragma unroll
            for (int kk = 0; kk < 4; kk++) {
                const unsigned kb = kk * 32;   // 16 halves = 32 bytes
                uint32_t a[4][4];
#pragma unroll
                for (int mf = 0; mf < 4; mf++)
                    LDSM_X4(a[mf][0], a[mf][1], a[mf][2], a[mf][3],
                            base + offA[mf] + kb);
                uint32_t bfr[2][4];
#pragma unroll
                for (int p = 0; p < 2; p++)
                    LDSM_X4(bfr[p][0], bfr[p][1], bfr[p][2], bfr[p][3],
                            base + offB[p] + kb);
#pragma unroll
                for (int nf = 0; nf < 4; nf++) {
                    const uint32_t b0 = bfr[nf >> 1][nf & 1];
                    const uint32_t b1 = bfr[nf >> 1][(nf & 1) + 2];
#pragma unroll
                    for (int mf = 0; mf < 4; mf++)
                        mma16h(acc[mf][nf], a[mf], b0, b1);
                }
            }
        }

        if (mode == 1 || mode == 2) {
            __syncthreads();   // compute done before reusing pipeline smem
            float* Cs = sm;    // 128 x 132 floats = 67584 B <= 110592
#pragma unroll
            for (int mf = 0; mf < 4; mf++) {
                const int row = wm * 64 + mf * 16 + g;
#pragma unroll
                for (int nf = 0; nf < 4; nf++) {
                    const int col = wn * 32 + nf * 8 + 2 * c;
                    *(float2*)&Cs[row * 132 + col] =
                        make_float2(acc[mf][nf][0], acc[mf][nf][1]);
                    *(float2*)&Cs[(row + 8) * 132 + col] =
                        make_float2(acc[mf][nf][2], acc[mf][nf][3]);
                }
            }
            __syncthreads();
            // mode 1: log2(e)/sqrt(128) -> exp2-domain softmax downstream
            const float SC = (mode == 1) ? 0.12751747707857376f : 1.0f;
            for (int p = tid; p < 128 * 32; p += 256) {
                const int r  = p >> 5;
                const int f4 = (p & 31) << 2;
                const int m  = mbase + r;
                const int s  = m & (SEQ - 1);
                const float* crow = &Cs[r * 132];
                float v[4];
                if (f4 < 64) {
#pragma unroll
                    for (int e = 0; e < 4; e++) {
                        const int j = f4 + e;
                        const float cs = g_tcos[(s << 6) + j];
                        const float sn = g_tsin[(s << 6) + j];
                        v[e] = tf32r((crow[j] * cs - crow[2 * j + 1] * sn) * SC);
                    }
                } else {
#pragma unroll
                    for (int e = 0; e < 4; e++) {
                        const int j = f4 - 64 + e;
                        const float cs = g_tcos[(s << 6) + j];
                        const float sn = g_tsin[(s << 6) + j];
                        v[e] = tf32r((crow[j + 64] * cs + crow[2 * j] * sn) * SC);
                    }
                }
                *(float4*)&C[(size_t)m * DIMV + nbase + f4] =
                    make_float4(v[0], v[1], v[2], v[3]);
            }
        } else {
#pragma unroll
            for (int mf = 0; mf < 4; mf++) {
                const int row = mbase + wm * 64 + mf * 16 + g;
#pragma unroll
                for (int nf = 0; nf < 4; nf++) {
                    const int col = nbase + wn * 32 + nf * 8 + 2 * c;
                    float o0 = acc[mf][nf][0], o1 = acc[mf][nf][1];
                    float o2 = acc[mf][nf][2], o3 = acc[mf][nf][3];
                    if (mode == 3) {
                        o0 = tf32r(o0); o1 = tf32r(o1);
                        o2 = tf32r(o2); o3 = tf32r(o3);
                    }
                    *(float2*)&C[(size_t)row * DIMV + col] = make_float2(o0, o1);
                    *(float2*)&C[(size_t)(row + 8) * DIMV + col] =
                        make_float2(o2, o3);
                }
            }
        }
    }
}

// ---------------------------------------------------------------------------
// Causal flash attention (R15 version, tf32 path unchanged). One CTA runs
// the q-tile pair (31-i, i): exactly 33 kv-iters per CTA. exp2 softmax.
// Epilogue now emits HALF g_att (feeds the fp16 Wo GEMM).
// ---------------------------------------------------------------------------
#define QSTR 132
#define KSTR 132
#define VSTR 136
#define PSTR 68
#define KOFS (64 * QSTR)
#define VOFS (KOFS + 64 * KSTR)
#define FLASH_SMEM ((VOFS + 64 * VSTR) * 4)   // 102400

__global__ __launch_bounds__(128) void flash_kernel() {
    extern __shared__ float sm[];
    float* Qs = sm;
    float* Ks = sm + KOFS;     // re-used as P after the S phase
    float* Vs = sm + VOFS;

    const int tid  = threadIdx.x;
    const int lane = tid & 31;
    const int w    = tid >> 5;
    const int g    = lane >> 2;
    const int c    = lane & 3;

    const int h  = blockIdx.y;
    const int b  = blockIdx.z;
    const size_t brow = (size_t)b * SEQ;
    const int hcol = h * HDIM;
    const int NQT = SEQ / 64;   // 32

    const unsigned smB = smem_u32(sm);
    const int lm = lane >> 3, lrr = lane & 7;
    const unsigned offQ = (unsigned)(((w * 16 + (lm & 1) * 8 + lrr) * QSTR
                                      + (lm >> 1) * 4) * 4);
    unsigned offK[4];
#pragma unroll
    for (int p = 0; p < 4; p++)
        offK[p] = (unsigned)((KOFS + (p * 16 + (lm >> 1) * 8 + lrr) * KSTR
                              + (lm & 1) * 4) * 4);
    const unsigned offP = (unsigned)((KOFS + w * 16 * PSTR
                                      + ((lm & 1) * 8 + lrr) * PSTR
                                      + (lm >> 1) * 4) * 4);

    float* Pw = Ks + w * 16 * PSTR;   // alias into K region

    for (int half_i = 0; half_i < 2; half_i++) {
        const int qt = (half_i == 0) ? (NQT - 1 - (int)blockIdx.x)
                                     : (int)blockIdx.x;
        const int q0 = qt * 64;

        __syncthreads();   // prior half's P/V smem reads fully done

        for (int idx = tid; idx < 64 * 32; idx += 128) {
            int r = idx >> 5, d4 = (idx & 31) << 2;
            CP_ASYNC16(smem_u32(&Qs[r * QSTR + d4]),
                       &g_qr[(brow + q0 + r) * DIMV + hcol + d4]);
        }
        CP_COMMIT();

        float O[16][4];
#pragma unroll
        for (int nf = 0; nf < 16; nf++)
#pragma unroll
            for (int e = 0; e < 4; e++) O[nf][e] = 0.f;
        float m0 = -1e30f, m1 = -1e30f, l0 = 0.f, l1 = 0.f;

        for (int kt = 0; kt <= qt; kt++) {
            __syncthreads();
            for (int idx = tid; idx < 64 * 32; idx += 128) {
                int r = idx >> 5, d4 = (idx & 31) << 2;
                CP_ASYNC16(smem_u32(&Ks[r * KSTR + d4]),
                           &g_kr[(brow + (size_t)kt * 64 + r) * DIMV + hcol + d4]);
            }
            CP_COMMIT();
            for (int idx = tid; idx < 64 * 32; idx += 128) {
                int r = idx >> 5, d4 = (idx & 31) << 2;
                CP_ASYNC16(smem_u32(&Vs[r * VSTR + d4]),
                           &g_v[(brow + (size_t)kt * 64 + r) * DIMV + hcol + d4]);
            }
            CP_COMMIT();
            CP_WAIT1();
            __syncthreads();

            float sacc[8][4];
#pragma unroll
            for (int nf = 0; nf < 8; nf++)
#pragma unroll
                for (int e = 0; e < 4; e++) sacc[nf][e] = 0.f;

#pragma unroll
            for (int k0 = 0; k0 < 128; k0 += 8) {
                uint32_t a[4];
                LDSM_X4(a[0], a[1], a[2], a[3], smB + offQ + k0 * 4);
                uint32_t kb[4][4];
#pragma unroll
                for (int p = 0; p < 4; p++)
                    LDSM_X4(kb[p][0], kb[p][1], kb[p][2], kb[p][3],
                            smB + offK[p] + k0 * 4);
#pragma unroll
                for (int nf = 0; nf < 8; nf++)
                    mma8u(sacc[nf], a, kb[nf >> 1][(nf & 1) * 2],
                          kb[nf >> 1][(nf & 1) * 2 + 1]);
            }

            if (kt == qt) {
                const int r0 = w * 16 + g;
#pragma unroll
                for (int nf = 0; nf < 8; nf++) {
                    const int col0 = nf * 8 + 2 * c;
                    if (col0     > r0)     sacc[nf][0] = -1e30f;
                    if (col0 + 1 > r0)     sacc[nf][1] = -1e30f;
                    if (col0     > r0 + 8) sacc[nf][2] = -1e30f;
                    if (col0 + 1 > r0 + 8) sacc[nf][3] = -1e30f;
                }
            }

            float rm0 = -1e30f, rm1 = -1e30f;
#pragma unroll
            for (int nf = 0; nf < 8; nf++) {
                rm0 = fmaxf(rm0, fmaxf(sacc[nf][0], sacc[nf][1]));
                rm1 = fmaxf(rm1, fmaxf(sacc[nf][2], sacc[nf][3]));
            }
            rm0 = fmaxf(rm0, __shfl_xor_sync(0xffffffffu, rm0, 1));
            rm0 = fmaxf(rm0, __shfl_xor_sync(0xffffffffu, rm0, 2));
            rm1 = fmaxf(rm1, __shfl_xor_sync(0xffffffffu, rm1, 1));
            rm1 = fmaxf(rm1, __shfl_xor_sync(0xffffffffu, rm1, 2));

            const float mn0 = fmaxf(m0, rm0), mn1 = fmaxf(m1, rm1);
            const float al0 = exp2f(m0 - mn0), al1 = exp2f(m1 - mn1);

            float ps0 = 0.f, ps1 = 0.f;
#pragma unroll
            for (int nf = 0; nf < 8; nf++) {   // pure MUFU.EX2
                sacc[nf][0] = exp2f(sacc[nf][0] - mn0);
                sacc[nf][1] = exp2f(sacc[nf][1] - mn0);
                sacc[nf][2] = exp2f(sacc[nf][2] - mn1);
                sacc[nf][3] = exp2f(sacc[nf][3] - mn1);
                ps0 += sacc[nf][0] + sacc[nf][1];
                ps1 += sacc[nf][2] + sacc[nf][3];
            }
            ps0 += __shfl_xor_sync(0xffffffffu, ps0, 1);
            ps0 += __shfl_xor_sync(0xffffffffu, ps0, 2);
            ps1 += __shfl_xor_sync(0xffffffffu, ps1, 1);
            ps1 += __shfl_xor_sync(0xffffffffu, ps1, 2);
            l0 = l0 * al0 + ps0;
            l1 = l1 * al1 + ps1;
            m0 = mn0; m1 = mn1;

#pragma unroll
            for (int nf = 0; nf < 16; nf++) {
                O[nf][0] *= al0; O[nf][1] *= al0;
                O[nf][2] *= al1; O[nf][3] *= al1;
            }

            CP_WAIT0();        // V landed
            __syncthreads();   // K reads done before P overwrites

#pragma unroll
            for (int nf = 0; nf < 8; nf++) {
                const int col = nf * 8 + 2 * c;
                *(float2*)&Pw[g * PSTR + col] =
                    make_float2(tf32r(sacc[nf][0]), tf32r(sacc[nf][1]));
                *(float2*)&Pw[(g + 8) * PSTR + col] =
                    make_float2(tf32r(sacc[nf][2]), tf32r(sacc[nf][3]));
            }
            __syncwarp();

#pragma unroll
            for (int k0 = 0; k0 < 64; k0 += 8) {
                uint32_t a[4];
                LDSM_X4(a[0], a[1], a[2], a[3], smB + offP + k0 * 4);
#pragma unroll
                for (int nf = 0; nf < 16; nf++) {
                    const uint32_t b0 =
                        __float_as_uint(Vs[(k0 + c) * VSTR + nf * 8 + g]);
                    const uint32_t b1 =
                        __float_as_uint(Vs[(k0 + c + 4) * VSTR + nf * 8 + g]);
                    mma8u(O[nf], a, b0, b1);
                }
            }
        }

        // Epilogue: normalize, write HALF g_att (feeds fp16 Wo GEMM)
        const float r0 = 1.f / l0, r1 = 1.f / l1;
        const int qrow = q0 + w * 16 + g;
#pragma unroll
        for (int nf = 0; nf < 16; nf++) {
            const int col = hcol + nf * 8 + 2 * c;
            *(__half2*)&g_att[(brow + qrow) * DIMV + col] =
                __floats2half2_rn(O[nf][0] * r0, O[nf][1] * r0);
            *(__half2*)&g_att[(brow + qrow + 8) * DIMV + col] =
                __floats2half2_rn(O[nf][2] * r1, O[nf][3] * r1);
        }
    }
}

// ---------------------------------------------------------------------------
// Launch
// ---------------------------------------------------------------------------
extern "C" void kernel_launch(void* const* d_in, const int* in_sizes, int n_in,
                              void* d_out, int out_size) {
    (void)in_sizes; (void)n_in; (void)out_size;
    const float* x  = (const float*)d_in[0];
    const float* Wq = (const float*)d_in[1];
    const float* Wk = (const float*)d_in[2];
    const float* Wv = (const float*)d_in[3];
    const float* Wo = (const float*)d_in[4];
    float* out = (float*)d_out;

    float *pqr, *pkr, *pv;
    __half *patt, *pxh, *pwq, *pwk, *pwv, *pwo;
    cudaGetSymbolAddress((void**)&pqr,  g_qr);
    cudaGetSymbolAddress((void**)&pkr,  g_kr);
    cudaGetSymbolAddress((void**)&pv,   g_v);
    cudaGetSymbolAddress((void**)&patt, g_att);
    cudaGetSymbolAddress((void**)&pxh,  g_xh);
    cudaGetSymbolAddress((void**)&pwq,  g_wqh);
    cudaGetSymbolAddress((void**)&pwk,  g_wkh);
    cudaGetSymbolAddress((void**)&pwv,  g_wvh);
    cudaGetSymbolAddress((void**)&pwo,  g_woh);

    cudaFuncSetAttribute(gemm_nt,
                         cudaFuncAttributeMaxDynamicSharedMemorySize, GEMM_SMEM);
    cudaFuncSetAttribute(flash_kernel,
                         cudaFuncAttributeMaxDynamicSharedMemorySize, FLASH_SMEM);

    round_all<<<(NALL4 + 1023) / 1024, 256>>>(x, Wq, Wk, Wv, Wo);
    invf_kernel<<<1, 64>>>();
    rope_tables<<<(SEQ * 64 + 255) / 256, 256>>>();

    // QKV fused: 1536 tiles over 1480 CTAs (wave-packed; neutral but tidy)
    gemm_nt<<<1480, 256, GEMM_SMEM>>>(pxh, pwq, pwk, pwv,
                                      pqr, pkr, pv, 1, 2, 3, 1536);
    flash_kernel<<<dim3(SEQ / 128, NHEAD, 2), 128, FLASH_SMEM>>>();
    gemm_nt<<<512, 256, GEMM_SMEM>>>(patt, pwo, pwo, pwo,
                                     out, out, out, 0, 0, 0, 512);
}